// round 1
// baseline (speedup 1.0000x reference)
#include <cuda_runtime.h>

#define T_LEN   8192
#define THREADS 256
#define CHUNK   32          // T_LEN / THREADS
#define MOM     0.01f
#define DECAY   0.99f
#define DECAY32 0.7249803f  // 0.99^32

__device__ float g_corr[T_LEN];

// Fill bias-correction table: corr[t] = 1 / (1 - 0.99^(t+1)).
// For t >= ~1724 this is exactly 1.0f in fp32 (reference computes fp32 too),
// so the main kernel only reads the first 2048 entries.
__global__ void corr_kernel() {
    int t = blockIdx.x * blockDim.x + threadIdx.x;
    if (t < T_LEN) {
        float q = powf(DECAY, (float)(t + 1));
        g_corr[t] = 1.0f / (1.0f - q);
    }
}

__global__ __launch_bounds__(THREADS)
void ema_kernel(const float* __restrict__ x, float* __restrict__ out) {
    const int tid = threadIdx.x;
    const int t0  = tid * CHUNK;
    const long long base = (long long)blockIdx.x * T_LEN + t0;

    const float4* __restrict__ xin  = (const float4*)(x + base);
    float4* __restrict__       xout = (float4*)(out + base);

    // ---- load 32 contiguous elements (one 128B line per thread) ----
    float v[CHUNK];
#pragma unroll
    for (int i = 0; i < CHUNK / 4; i++) {
        float4 b = xin[i];
        v[4*i + 0] = b.x; v[4*i + 1] = b.y;
        v[4*i + 2] = b.z; v[4*i + 3] = b.w;
    }

    // ---- local EMA scan in registers ----
    float y = 0.0f;
#pragma unroll
    for (int j = 0; j < CHUNK; j++) {
        y = fmaf(DECAY, y, MOM * v[j]);
        v[j] = y;                       // y now = chunk-local EMA, zero carry-in
    }

    // ---- block-level scan of (decay^32, last) affine pairs ----
    __shared__ float sp[THREADS];
    __shared__ float sv[THREADS];
    sp[tid] = DECAY32;
    sv[tid] = y;
    __syncthreads();
#pragma unroll
    for (int off = 1; off < THREADS; off <<= 1) {
        float pp = 0.0f, vp = 0.0f;
        const bool act = (tid >= off);
        if (act) { pp = sp[tid - off]; vp = sv[tid - off]; }
        __syncthreads();
        if (act) {
            // (pp,vp) ∘ (p,v) = (pp*p, v + p*vp)
            sv[tid] = fmaf(sp[tid], vp, sv[tid]);
            sp[tid] *= pp;
        }
        __syncthreads();
    }
    const float cin = (tid == 0) ? 0.0f : sv[tid - 1];

    // ---- apply carry: v[j] += cin * 0.99^(j+1) ----
    float ap = DECAY;
#pragma unroll
    for (int j = 0; j < CHUNK; j++) {
        v[j] = fmaf(cin, ap, v[j]);
        ap *= DECAY;
    }

    // ---- bias correction (exactly 1.0f beyond t ~ 1724; skip there) ----
    if (t0 < 2048) {
        const float4* __restrict__ cp = (const float4*)(g_corr + t0);
#pragma unroll
        for (int i = 0; i < CHUNK / 4; i++) {
            float4 c = cp[i];
            v[4*i + 0] *= c.x; v[4*i + 1] *= c.y;
            v[4*i + 2] *= c.z; v[4*i + 3] *= c.w;
        }
    }

    // ---- store ----
#pragma unroll
    for (int i = 0; i < CHUNK / 4; i++) {
        float4 o;
        o.x = v[4*i + 0]; o.y = v[4*i + 1];
        o.z = v[4*i + 2]; o.w = v[4*i + 3];
        xout[i] = o;
    }
}

extern "C" void kernel_launch(void* const* d_in, const int* in_sizes, int n_in,
                              void* d_out, int out_size) {
    const float* x   = (const float*)d_in[0];
    float*       out = (float*)d_out;
    const int rows   = in_sizes[0] / T_LEN;   // 32*256 = 8192

    corr_kernel<<<(T_LEN + 255) / 256, 256>>>();
    ema_kernel<<<rows, THREADS>>>(x, out);
}

// round 2
// speedup vs baseline: 1.6895x; 1.6895x over previous
#include <cuda_runtime.h>

#define T_LEN   8192
#define THREADS 256
#define CHUNK   32          // T_LEN / THREADS
#define MOM     0.01f
#define DECAY   0.99f
#define DECAY32 0.7249803f  // 0.99^32

// padded smem index: +4 floats per 32 (keeps float4 alignment, kills conflicts)
#define PADIDX(i) ((i) + (((i) >> 5) << 2))
#define TILE_F  (T_LEN + (T_LEN / 32) * 4)   // 9216 floats = 36 KB

__device__ float g_corr[T_LEN];

// corr[t] = 1 / (1 - 0.99^(t+1)); exactly 1.0f in fp32 for t >= ~1724.
__global__ void corr_kernel() {
    int t = blockIdx.x * blockDim.x + threadIdx.x;
    if (t < T_LEN) {
        float q = powf(DECAY, (float)(t + 1));
        g_corr[t] = 1.0f / (1.0f - q);
    }
}

__global__ __launch_bounds__(THREADS)
void ema_kernel(const float* __restrict__ x, float* __restrict__ out) {
    __shared__ float tile[TILE_F];

    const int tid = threadIdx.x;
    const long long rowbase = (long long)blockIdx.x * T_LEN;
    const float4* __restrict__ xin4  = (const float4*)(x + rowbase);
    float4* __restrict__       xout4 = (float4*)(out + rowbase);

    // ---- Phase 1: coalesced global load -> padded smem tile ----
#pragma unroll
    for (int i = 0; i < T_LEN / 4 / THREADS; i++) {     // 8 iters
        int idx4 = i * THREADS + tid;                   // float4 index
        float4 b = xin4[idx4];
        int f = idx4 * 4;
        *(float4*)&tile[PADIDX(f)] = b;                 // conflict-free STS.128
    }
    __syncthreads();

    // ---- Phase 2: each thread reads its contiguous 32-elem chunk ----
    const int t0 = tid * CHUNK;
    float v[CHUNK];
#pragma unroll
    for (int k = 0; k < CHUNK / 4; k++) {
        float4 b = *(const float4*)&tile[tid * 36 + 4 * k];  // PADIDX(t0+4k)
        v[4*k + 0] = b.x; v[4*k + 1] = b.y;
        v[4*k + 2] = b.z; v[4*k + 3] = b.w;
    }
    __syncthreads();   // tile reads done; safe to alias scan arrays below

    // ---- local EMA scan in registers ----
    float y = 0.0f;
#pragma unroll
    for (int j = 0; j < CHUNK; j++) {
        y = fmaf(DECAY, y, MOM * v[j]);
        v[j] = y;
    }

    // ---- block-level scan of (decay^32, last) affine pairs (aliased in tile) ----
    float* sp = tile;            // [0,256)
    float* sv = tile + THREADS;  // [256,512)
    sp[tid] = DECAY32;
    sv[tid] = y;
    __syncthreads();
#pragma unroll
    for (int off = 1; off < THREADS; off <<= 1) {
        float pp = 0.0f, vp = 0.0f;
        const bool act = (tid >= off);
        if (act) { pp = sp[tid - off]; vp = sv[tid - off]; }
        __syncthreads();
        if (act) {
            sv[tid] = fmaf(sp[tid], vp, sv[tid]);   // (pp,vp)∘(p,v)
            sp[tid] *= pp;
        }
        __syncthreads();
    }
    const float cin = (tid == 0) ? 0.0f : sv[tid - 1];
    __syncthreads();   // everyone has cin; safe to overwrite tile

    // ---- apply carry: v[j] += cin * 0.99^(j+1) ----
    float ap = DECAY;
#pragma unroll
    for (int j = 0; j < CHUNK; j++) {
        v[j] = fmaf(cin, ap, v[j]);
        ap *= DECAY;
    }

    // ---- bias correction (identically 1.0f beyond t ~1724; skip there) ----
    if (t0 < 2048) {
        const float4* __restrict__ cp = (const float4*)(g_corr + t0);
#pragma unroll
        for (int k = 0; k < CHUNK / 4; k++) {
            float4 c = cp[k];
            v[4*k + 0] *= c.x; v[4*k + 1] *= c.y;
            v[4*k + 2] *= c.z; v[4*k + 3] *= c.w;
        }
    }

    // ---- Phase 3: results -> padded tile -> coalesced global store ----
#pragma unroll
    for (int k = 0; k < CHUNK / 4; k++) {
        float4 o;
        o.x = v[4*k + 0]; o.y = v[4*k + 1];
        o.z = v[4*k + 2]; o.w = v[4*k + 3];
        *(float4*)&tile[tid * 36 + 4 * k] = o;          // conflict-free STS.128
    }
    __syncthreads();
#pragma unroll
    for (int i = 0; i < T_LEN / 4 / THREADS; i++) {
        int idx4 = i * THREADS + tid;
        int f = idx4 * 4;
        float4 b = *(const float4*)&tile[PADIDX(f)];    // conflict-free LDS.128
        xout4[idx4] = b;
    }
}

extern "C" void kernel_launch(void* const* d_in, const int* in_sizes, int n_in,
                              void* d_out, int out_size) {
    const float* x   = (const float*)d_in[0];
    float*       out = (float*)d_out;
    const int rows   = in_sizes[0] / T_LEN;   // 8192

    corr_kernel<<<(T_LEN + 255) / 256, 256>>>();
    ema_kernel<<<rows, THREADS>>>(x, out);
}

// round 3
// speedup vs baseline: 1.9561x; 1.1578x over previous
#include <cuda_runtime.h>

#define T_LEN   8192
#define THREADS 256
#define MOM     0.01f

// compile-time decay powers (folded from double)
constexpr double Dd    = 0.99;
constexpr double D2d   = Dd * Dd;
constexpr double D3d   = D2d * Dd;
constexpr double D4d   = D2d * D2d;
constexpr double D8d   = D4d * D4d;
constexpr double D16d  = D8d * D8d;
constexpr double D32d  = D16d * D16d;
constexpr double D64d  = D32d * D32d;
constexpr double D128d = D64d * D64d;
constexpr double D256d = D128d * D128d;
constexpr double D512d = D256d * D256d;
constexpr double D1024d = D512d * D512d;

#define D1f    ((float)Dd)
#define D2f    ((float)D2d)
#define D3f    ((float)D3d)
#define D4f    ((float)D4d)
#define D8f    ((float)D8d)
#define D16f   ((float)D16d)
#define D32f   ((float)D32d)
#define D64f   ((float)D64d)
#define D128f  ((float)D128d)
#define D1024f ((float)D1024d)

// corr[t] = 1/(1 - 0.99^(t+1)); exactly 1.0f in fp32 for t >= ~1724,
// so only the first 2048 entries are ever needed.
__device__ float g_corr[2048];

__global__ void corr_kernel() {
    int t = blockIdx.x * blockDim.x + threadIdx.x;
    if (t < 2048) {
        float q = powf(0.99f, (float)(t + 1));
        g_corr[t] = 1.0f / (1.0f - q);
    }
}

__global__ __launch_bounds__(THREADS, 4)
void ema_kernel(const float* __restrict__ x, float* __restrict__ out) {
    const int tid  = threadIdx.x;
    const int lane = tid & 31;
    const int w    = tid >> 5;                 // warp 0..7, owns 1024 contiguous elems
    const int seg  = w << 10;
    const long long rowbase = (long long)blockIdx.x * T_LEN;

    const float4* __restrict__ xin = (const float4*)(x + rowbase + seg);
    float4* __restrict__       xo  = (float4*)(out + rowbase + seg);

    // d^(4*lane) from bit decomposition (exact-ish constant chain)
    float dp4l = 1.0f;
    if (lane & 1)  dp4l *= D4f;
    if (lane & 2)  dp4l *= D8f;
    if (lane & 4)  dp4l *= D16f;
    if (lane & 8)  dp4l *= D32f;
    if (lane & 16) dp4l *= D64f;

    // ---- load 8 blocks, fully coalesced (lane l -> bytes 16l..16l+15 of each 512B block)
    float4 vv[8];
#pragma unroll
    for (int k = 0; k < 8; k++) vv[k] = xin[k * 32 + lane];

    // ---- per-warp scan: 8 blocks of 128 elems, carry chained ----
    float carry = 0.0f;   // EMA value just before current block (uniform across lanes)
#pragma unroll
    for (int k = 0; k < 8; k++) {
        // local 4-elem EMA with zero carry-in
        float z0 = MOM * vv[k].x;
        float z1 = fmaf(D1f, z0, MOM * vv[k].y);
        float z2 = fmaf(D1f, z1, MOM * vv[k].z);
        float z3 = fmaf(D1f, z2, MOM * vv[k].w);

        // inclusive affine lane-scan of z3 with transfer factor d^4
        float I = z3, u;
        u = __shfl_up_sync(0xffffffffu, I, 1);  if (lane >= 1)  I = fmaf(D4f,  u, I);
        u = __shfl_up_sync(0xffffffffu, I, 2);  if (lane >= 2)  I = fmaf(D8f,  u, I);
        u = __shfl_up_sync(0xffffffffu, I, 4);  if (lane >= 4)  I = fmaf(D16f, u, I);
        u = __shfl_up_sync(0xffffffffu, I, 8);  if (lane >= 8)  I = fmaf(D32f, u, I);
        u = __shfl_up_sync(0xffffffffu, I, 16); if (lane >= 16) I = fmaf(D64f, u, I);

        // exclusive prefix + block carry -> carry into this lane
        float E = __shfl_up_sync(0xffffffffu, I, 1);
        if (lane == 0) E = 0.0f;
        float F = fmaf(dp4l, carry, E);

        vv[k].x = fmaf(D1f, F, z0);
        vv[k].y = fmaf(D2f, F, z1);
        vv[k].z = fmaf(D3f, F, z2);
        vv[k].w = fmaf(D4f, F, z3);

        // next block carry = I[31] + d^128 * carry   (uniform)
        float I31 = __shfl_sync(0xffffffffu, I, 31);
        carry = fmaf(D128f, carry, I31);
    }

    // ---- cross-warp carry combine (8 floats of smem, one barrier) ----
    __shared__ float s_c[8];
    if (lane == 0) s_c[w] = carry;
    __syncthreads();
    float cin = 0.0f;
    for (int ww = 0; ww < w; ww++)
        cin = fmaf(D1024f, cin, s_c[ww]);

    // apply segment carry: v[128k+4l+i] += cin * d^(128k+4l+i+1)
    float g  = cin * dp4l;
    float fk = 1.0f;
#pragma unroll
    for (int k = 0; k < 8; k++) {
        float h = g * fk;
        vv[k].x = fmaf(h, D1f, vv[k].x);
        vv[k].y = fmaf(h, D2f, vv[k].y);
        vv[k].z = fmaf(h, D3f, vv[k].z);
        vv[k].w = fmaf(h, D4f, vv[k].w);
        fk *= D128f;
    }

    // ---- bias correction: only t < 2048 (warps 0 and 1), coalesced table reads ----
    if (seg < 2048) {
        const float4* __restrict__ cp = (const float4*)(g_corr + seg);
#pragma unroll
        for (int k = 0; k < 8; k++) {
            float4 c = cp[k * 32 + lane];
            vv[k].x *= c.x; vv[k].y *= c.y;
            vv[k].z *= c.z; vv[k].w *= c.w;
        }
    }

    // ---- coalesced store ----
#pragma unroll
    for (int k = 0; k < 8; k++) xo[k * 32 + lane] = vv[k];
}

extern "C" void kernel_launch(void* const* d_in, const int* in_sizes, int n_in,
                              void* d_out, int out_size) {
    const float* x   = (const float*)d_in[0];
    float*       out = (float*)d_out;
    const int rows   = in_sizes[0] / T_LEN;   // 8192

    corr_kernel<<<8, 256>>>();
    ema_kernel<<<rows, THREADS>>>(x, out);
}

// round 4
// speedup vs baseline: 2.0233x; 1.0344x over previous
#include <cuda_runtime.h>

#define T_LEN   8192
#define THREADS 512
#define MOM     0.01f

// compile-time decay powers (folded from double)
constexpr double Dd    = 0.99;
constexpr double D2d   = Dd * Dd;
constexpr double D3d   = D2d * Dd;
constexpr double D4d   = D2d * D2d;
constexpr double D8d   = D4d * D4d;
constexpr double D16d  = D8d * D8d;
constexpr double D32d  = D16d * D16d;
constexpr double D64d  = D32d * D32d;
constexpr double D128d = D64d * D64d;
constexpr double D256d = D128d * D128d;
constexpr double D512d = D256d * D256d;

#define D1f   ((float)Dd)
#define D2f   ((float)D2d)
#define D3f   ((float)D3d)
#define D4f   ((float)D4d)
#define D8f   ((float)D8d)
#define D16f  ((float)D16d)
#define D32f  ((float)D32d)
#define D64f  ((float)D64d)
#define D128f ((float)D128d)
#define D512f ((float)D512d)

#define LOG2_D (-0.014499569695115089f)   // log2(0.99)

__global__ __launch_bounds__(THREADS, 3)
void ema_kernel(const float* __restrict__ x, float* __restrict__ out) {
    const int tid  = threadIdx.x;
    const int lane = tid & 31;
    const int w    = tid >> 5;                 // warp 0..15, owns 512 contiguous elems
    const int seg  = w << 9;
    const long long rowbase = (long long)blockIdx.x * T_LEN;

    const float4* __restrict__ xin = (const float4*)(x + rowbase + seg);
    float4* __restrict__       xo  = (float4*)(out + rowbase + seg);

    // d^(4*lane) via bit decomposition
    float dp4l = 1.0f;
    if (lane & 1)  dp4l *= D4f;
    if (lane & 2)  dp4l *= D8f;
    if (lane & 4)  dp4l *= D16f;
    if (lane & 8)  dp4l *= D32f;
    if (lane & 16) dp4l *= D64f;

    // ---- load 4 blocks of 128, fully coalesced ----
    float4 vv[4];
#pragma unroll
    for (int k = 0; k < 4; k++) vv[k] = xin[k * 32 + lane];

    // ---- per-warp scan: 4 blocks of 128 elems, carry chained ----
    float carry = 0.0f;   // EMA value just before current block (uniform)
#pragma unroll
    for (int k = 0; k < 4; k++) {
        // local 4-elem EMA with zero carry-in
        float z0 = MOM * vv[k].x;
        float z1 = fmaf(D1f, z0, MOM * vv[k].y);
        float z2 = fmaf(D1f, z1, MOM * vv[k].z);
        float z3 = fmaf(D1f, z2, MOM * vv[k].w);

        // inclusive affine lane-scan of z3, transfer factor d^4
        float I = z3, u;
        u = __shfl_up_sync(0xffffffffu, I, 1);  if (lane >= 1)  I = fmaf(D4f,  u, I);
        u = __shfl_up_sync(0xffffffffu, I, 2);  if (lane >= 2)  I = fmaf(D8f,  u, I);
        u = __shfl_up_sync(0xffffffffu, I, 4);  if (lane >= 4)  I = fmaf(D16f, u, I);
        u = __shfl_up_sync(0xffffffffu, I, 8);  if (lane >= 8)  I = fmaf(D32f, u, I);
        u = __shfl_up_sync(0xffffffffu, I, 16); if (lane >= 16) I = fmaf(D64f, u, I);

        // exclusive prefix + block carry
        float E = __shfl_up_sync(0xffffffffu, I, 1);
        if (lane == 0) E = 0.0f;
        float F = fmaf(dp4l, carry, E);

        vv[k].x = fmaf(D1f, F, z0);
        vv[k].y = fmaf(D2f, F, z1);
        vv[k].z = fmaf(D3f, F, z2);
        vv[k].w = fmaf(D4f, F, z3);

        float I31 = __shfl_sync(0xffffffffu, I, 31);
        carry = fmaf(D128f, carry, I31);
    }

    // ---- cross-warp carry combine (16 floats smem, one barrier) ----
    __shared__ float s_c[16];
    if (lane == 0) s_c[w] = carry;
    __syncthreads();
    float cin = 0.0f;
    for (int ww = 0; ww < w; ww++)
        cin = fmaf(D512f, cin, s_c[ww]);

    // apply segment carry: v[128k+4l+i] += cin * d^(128k+4l+i+1)
    float g  = cin * dp4l;
    float fk = 1.0f;
#pragma unroll
    for (int k = 0; k < 4; k++) {
        float h = g * fk;
        vv[k].x = fmaf(h, D1f, vv[k].x);
        vv[k].y = fmaf(h, D2f, vv[k].y);
        vv[k].z = fmaf(h, D3f, vv[k].z);
        vv[k].w = fmaf(h, D4f, vv[k].w);
        fk *= D128f;
    }

    // ---- bias correction (t < 2048 only: warps 0..3) fused with store ----
    const bool needc = (seg < 2048);
#pragma unroll
    for (int k = 0; k < 4; k++) {
        float4 o = vv[k];
        if (needc) {
            float tb = (float)(seg + 128 * k + 4 * lane + 1);   // t+1 of o.x
            float qx = exp2f(LOG2_D * tb);
            float qy = exp2f(LOG2_D * (tb + 1.0f));
            float qz = exp2f(LOG2_D * (tb + 2.0f));
            float qw = exp2f(LOG2_D * (tb + 3.0f));
            o.x = __fdividef(o.x, 1.0f - qx);
            o.y = __fdividef(o.y, 1.0f - qy);
            o.z = __fdividef(o.z, 1.0f - qz);
            o.w = __fdividef(o.w, 1.0f - qw);
        }
        xo[k * 32 + lane] = o;
    }
}

extern "C" void kernel_launch(void* const* d_in, const int* in_sizes, int n_in,
                              void* d_out, int out_size) {
    const float* x   = (const float*)d_in[0];
    float*       out = (float*)d_out;
    const int rows   = in_sizes[0] / T_LEN;   // 8192

    ema_kernel<<<rows, THREADS>>>(x, out);
}